// round 6
// baseline (speedup 1.0000x reference)
#include <cuda_runtime.h>
#include <cuda_fp16.h>
#include <cstdint>
#include <cstddef>

// ---------------------------------------------------------------------------
// Problem constants
// ---------------------------------------------------------------------------
constexpr int B_ = 256;   // batches
constexpr int N_ = 1024;  // patches
constexpr int M_ = 128;   // words
constexpr int C_ = 512;   // channels (K)

constexpr int NTILE  = 128;          // patch tile
constexpr int NTILES = N_ / NTILE;   // 8
constexpr int KC     = 32;           // K chunk (fp32 elements)
constexpr int KCH    = C_ / KC;      // 16
constexpr int GTOT   = NTILES * KCH; // 128 chunks

// Word tile: fully SMEM-resident, fp16, row stride 520 halfs (512 + 8 pad).
// 520*2 = 1040 B = 260 words -> 260 % 32 = 4: 8-row ldmatrix phases hit
// banks {0,4,...,28}+quad -> conflict-free.
constexpr int WSTR       = 520;
constexpr int WORD_BYTES = M_ * WSTR * 2;          // 133120

// Patch chunk buffers: 128 rows x 40 halfs (32 + 8 pad), double buffered
constexpr int SPH        = 40;
constexpr int PBUF_BYTES = NTILE * SPH * 2;        // 10240
constexpr int POFF       = WORD_BYTES;             // patch buf 0 at byte 133120

// Float-indexed regions after word + 2 patch buffers
constexpr int MASKF   = (WORD_BYTES + 2 * PBUF_BYTES) / 4;  // 38400 (1024 floats)
constexpr int COLWF   = MASKF + 1024;                       // 4 x 128
constexpr int ROWREDF = COLWF + 512;                        // 128 x 2
constexpr int REDF    = ROWREDF + 256;                      // 32
constexpr int SMEM_BYTES = (REDF + 32) * 4;                 // 160896

// ---------------------------------------------------------------------------
// Helpers
// ---------------------------------------------------------------------------
__device__ __forceinline__ uint32_t smem_u32(const void* p) {
    uint32_t a;
    asm("{ .reg .u64 t; cvta.to.shared.u64 t, %1; cvt.u32.u64 %0, t; }"
        : "=r"(a) : "l"(p));
    return a;
}

__device__ __forceinline__ void ldm4(uint32_t* r, uint32_t addr) {
    asm volatile("ldmatrix.sync.aligned.m8n8.x4.shared.b16 {%0,%1,%2,%3}, [%4];"
                 : "=r"(r[0]), "=r"(r[1]), "=r"(r[2]), "=r"(r[3]) : "r"(addr));
}

// m16n8k16 row.col fp16 mma, fp32 accumulate (C==D)
__device__ __forceinline__ void mma16(float* c, const uint32_t* a,
                                      uint32_t b0, uint32_t b1) {
    asm volatile(
        "mma.sync.aligned.m16n8k16.row.col.f32.f16.f16.f32 "
        "{%0,%1,%2,%3}, {%4,%5,%6,%7}, {%8,%9}, {%0,%1,%2,%3};"
        : "+f"(c[0]), "+f"(c[1]), "+f"(c[2]), "+f"(c[3])
        : "r"(a[0]), "r"(a[1]), "r"(a[2]), "r"(a[3]), "r"(b0), "r"(b1));
}

// ---------------------------------------------------------------------------
// Kernel: one CTA per batch; 256 threads = 8 warps (4 M x 2 N).
// Word (128x512) lives in SMEM as fp16 for the whole kernel; patch streams
// through a double-buffered 128x32 chunk pipe. DRAM traffic = the 577 MB floor.
// ---------------------------------------------------------------------------
__global__ void __launch_bounds__(256, 1)
hrpa_kernel(const float* __restrict__ patch,   // (B, N, C)
            const float* __restrict__ word,    // (B, M, C)
            const float* __restrict__ mask,    // (B, N)
            float* __restrict__ out)           // (B, 1)
{
    extern __shared__ char smc[];
    float* fsm = reinterpret_cast<float*>(smc);
    const uint32_t smb = smem_u32(smc);

    const int tid  = threadIdx.x;
    const int lane = tid & 31;
    const int w    = tid >> 5;
    const int wm   = w & 3;        // M direction (rows wm*32 .. +31)
    const int wn   = w >> 2;       // N direction (cols wn*64 .. +63)
    const int g    = lane >> 2;    // quad group 0..7
    const int tig  = lane & 3;     // thread in group
    const int b    = blockIdx.x;

    // ldmatrix per-thread offsets (half units)
    const int mi = lane >> 3, r8 = lane & 7;
    const int aoff = (((mi & 1) << 3) + r8) * WSTR + ((mi >> 1) << 3);  // word (stride 520)
    const int boff = (((mi >> 1) << 3) + r8) * SPH + ((mi & 1) << 3);   // patch (stride 40)

    const float* wbase = word  + (size_t)b * M_ * C_;
    const float* pbase = patch + (size_t)b * N_ * C_;

    // loader mapping: row = p*32 + (tid>>3), vec4 index = tid&7
    const int lr = tid >> 3;
    const int lv = tid & 7;

    // ---- mask -> smem, accumulate mask sum ----
    float masksum = 0.f;
    for (int i = tid; i < N_; i += 256) {
        float m = mask[b * N_ + i];
        fsm[MASKF + i] = m;
        masksum += m;
    }

    // ---- word -> smem (fp32 -> fp16), whole 128x512 ----
    #pragma unroll
    for (int kc = 0; kc < KCH; kc++) {
        #pragma unroll
        for (int p = 0; p < 4; p++) {
            const int r = p * 32 + lr;
            float4 v = *(const float4*)(wbase + (size_t)r * C_ + kc * KC + lv * 4);
            __half2 h0 = __floats2half2_rn(v.x, v.y);
            __half2 h1 = __floats2half2_rn(v.z, v.w);
            *(uint2*)(smc + (r * WSTR + kc * KC + lv * 4) * 2) =
                make_uint2(*(uint32_t*)&h0, *(uint32_t*)&h1);
        }
    }

    auto load_pregs = [&](int gq, float4* st) {
        const int nt = gq >> 4;
        const int k0 = (gq & 15) * KC;
        #pragma unroll
        for (int p = 0; p < 4; p++) {
            const int r = p * 32 + lr;
            st[p] = *(const float4*)(pbase + (size_t)(nt * NTILE + r) * C_ + k0 + lv * 4);
        }
    };
    auto sts_pstage = [&](int buf, const float4* st) {
        char* base = smc + POFF + buf * PBUF_BYTES;
        #pragma unroll
        for (int p = 0; p < 4; p++) {
            const int r = p * 32 + lr;
            __half2 h0 = __floats2half2_rn(st[p].x, st[p].y);
            __half2 h1 = __floats2half2_rn(st[p].z, st[p].w);
            *(uint2*)(base + (r * SPH + lv * 4) * 2) =
                make_uint2(*(uint32_t*)&h0, *(uint32_t*)&h1);
        }
    };

    // prologue: patch chunk 0 -> buffer 0
    {
        float4 sB[4];
        load_pregs(0, sB);
        sts_pstage(0, sB);
    }
    __syncthreads();

    float rmax[4] = {-3.0e38f, -3.0e38f, -3.0e38f, -3.0e38f};
    float colsum = 0.f;

    for (int nt = 0; nt < NTILES; nt++) {
        float acc[2][8][4];
        #pragma unroll
        for (int mt = 0; mt < 2; mt++)
            #pragma unroll
            for (int j = 0; j < 8; j++)
                #pragma unroll
                for (int q = 0; q < 4; q++) acc[mt][j][q] = 0.f;

        for (int kc = 0; kc < KCH; kc++) {
            const int gq  = nt * KCH + kc;
            const int buf = gq & 1;
            const bool more = (gq + 1 < GTOT);

            // prefetch next patch chunk into registers
            float4 sB[4];
            if (more) load_pregs(gq + 1, sB);

            // ---- MMAs: word (resident) x patch chunk ----
            const uint32_t bbase = smb + POFF + buf * PBUF_BYTES;
            #pragma unroll
            for (int ks = 0; ks < 2; ks++) {
                uint32_t A0[4], A1[4];
                const uint32_t acol = (uint32_t)(kc * KC + ks * 16);
                ldm4(A0, smb + (uint32_t)((wm * 32     ) * WSTR + acol + aoff) * 2);
                ldm4(A1, smb + (uint32_t)((wm * 32 + 16) * WSTR + acol + aoff) * 2);
                #pragma unroll
                for (int jj = 0; jj < 4; jj++) {
                    uint32_t Bf[4];
                    ldm4(Bf, bbase + (uint32_t)(((wn * 64 + jj * 16) * SPH) + boff + ks * 16) * 2);
                    mma16(acc[0][jj * 2    ], A0, Bf[0], Bf[1]);
                    mma16(acc[1][jj * 2    ], A1, Bf[0], Bf[1]);
                    mma16(acc[0][jj * 2 + 1], A0, Bf[2], Bf[3]);
                    mma16(acc[1][jj * 2 + 1], A1, Bf[2], Bf[3]);
                }
            }

            if (more) sts_pstage(buf ^ 1, sB);
            __syncthreads();
        }

        // ---- epilogue for this ntile ----
        // Thread owns rows {wm*32+mt*16+g, +8}, cols {wn*64+j*8+2tig, +1}.
        float colpart[16];
        #pragma unroll
        for (int j = 0; j < 8; j++) {
            #pragma unroll
            for (int cc = 0; cc < 2; cc++) {
                const int col = wn * 64 + j * 8 + 2 * tig + cc;
                const float pen = 1000.f * (1.f - fsm[MASKF + nt * NTILE + col]);
                float vmax = -3.0e38f;
                #pragma unroll
                for (int mt = 0; mt < 2; mt++) {
                    float v0 = acc[mt][j][cc];      // row m0+g
                    float v1 = acc[mt][j][cc + 2];  // row m0+8+g
                    v0 = v0 > 0.f ? v0 : 0.1f * v0;
                    v1 = v1 > 0.f ? v1 : 0.1f * v1;
                    rmax[mt * 2 + 0] = fmaxf(rmax[mt * 2 + 0], v0 - pen);
                    rmax[mt * 2 + 1] = fmaxf(rmax[mt * 2 + 1], v1 - pen);
                    vmax = fmaxf(vmax, fmaxf(v0, v1));
                }
                colpart[j * 2 + cc] = vmax;
            }
        }
        // column max across the 8 quad-groups
        #pragma unroll
        for (int off = 4; off <= 16; off <<= 1)
            #pragma unroll
            for (int i = 0; i < 16; i++)
                colpart[i] = fmaxf(colpart[i], __shfl_xor_sync(0xffffffffu, colpart[i], off));
        if (g == 0) {
            #pragma unroll
            for (int j = 0; j < 8; j++)
                #pragma unroll
                for (int cc = 0; cc < 2; cc++)
                    fsm[COLWF + wm * 128 + wn * 64 + j * 8 + 2 * tig + cc] =
                        colpart[j * 2 + cc];
        }
        __syncthreads();
        if (tid < 128) {
            const float cm = fmaxf(fmaxf(fsm[COLWF + tid], fsm[COLWF + 128 + tid]),
                                   fmaxf(fsm[COLWF + 256 + tid], fsm[COLWF + 384 + tid]));
            colsum += cm * fsm[MASKF + nt * NTILE + tid];
        }
        __syncthreads();
    }

    // ---- row-max combine (within quad, then across warps) ----
    #pragma unroll
    for (int off = 1; off <= 2; off <<= 1)
        #pragma unroll
        for (int i = 0; i < 4; i++)
            rmax[i] = fmaxf(rmax[i], __shfl_xor_sync(0xffffffffu, rmax[i], off));
    if (tig == 0) {
        #pragma unroll
        for (int mt = 0; mt < 2; mt++) {
            fsm[ROWREDF + (wm * 32 + mt * 16 +     g) * 2 + wn] = rmax[mt * 2 + 0];
            fsm[ROWREDF + (wm * 32 + mt * 16 + 8 + g) * 2 + wn] = rmax[mt * 2 + 1];
        }
    }
    __syncthreads();

    float rpart = 0.f;
    if (tid < 128)
        rpart = fmaxf(fsm[ROWREDF + tid * 2], fsm[ROWREDF + tid * 2 + 1]);

    // ---- block reduction of rpart / colsum / masksum ----
    #pragma unroll
    for (int off = 16; off > 0; off >>= 1) {
        rpart   += __shfl_down_sync(0xffffffffu, rpart,   off);
        colsum  += __shfl_down_sync(0xffffffffu, colsum,  off);
        masksum += __shfl_down_sync(0xffffffffu, masksum, off);
    }
    if (lane == 0) {
        fsm[REDF + w * 4 + 0] = rpart;
        fsm[REDF + w * 4 + 1] = colsum;
        fsm[REDF + w * 4 + 2] = masksum;
    }
    __syncthreads();
    if (tid == 0) {
        float rs = 0.f, cs = 0.f, ms = 0.f;
        #pragma unroll
        for (int i = 0; i < 8; i++) {
            rs += fsm[REDF + i * 4 + 0];
            cs += fsm[REDF + i * 4 + 1];
            ms += fsm[REDF + i * 4 + 2];
        }
        out[b] = rs * (1.f / 128.f) + cs / (ms + 1e-8f);
    }
}

// ---------------------------------------------------------------------------
// Host launch
// ---------------------------------------------------------------------------
extern "C" void kernel_launch(void* const* d_in, const int* in_sizes, int n_in,
                              void* d_out, int out_size)
{
    (void)in_sizes; (void)n_in; (void)out_size;
    const float* patch = (const float*)d_in[0];  // (B, N, C)
    const float* word  = (const float*)d_in[1];  // (B, M, C)
    const float* mask  = (const float*)d_in[2];  // (B, N)
    float* out = (float*)d_out;                  // (B, 1)

    cudaFuncSetAttribute(hrpa_kernel,
                         cudaFuncAttributeMaxDynamicSharedMemorySize, SMEM_BYTES);
    hrpa_kernel<<<B_, 256, SMEM_BYTES>>>(patch, word, mask, out);
}

// round 7
// speedup vs baseline: 1.5108x; 1.5108x over previous
#include <cuda_runtime.h>
#include <cuda_fp16.h>
#include <cstdint>
#include <cstddef>

// ---------------------------------------------------------------------------
// Problem constants
// ---------------------------------------------------------------------------
constexpr int B_ = 256;   // batches
constexpr int N_ = 1024;  // patches
constexpr int M_ = 128;   // words
constexpr int C_ = 512;   // channels (K)

constexpr int NTILE  = 256;          // patch tile (CTA N)
constexpr int NTILES = N_ / NTILE;   // 4
constexpr int KC     = 32;           // K chunk (fp32 elements)
constexpr int KCH    = C_ / KC;      // 16
constexpr int GTOT   = NTILES * KCH; // 64 chunks
constexpr int SPH    = 40;           // smem row stride in halfs (32 + 8 pad)

// Stage buffer geometry (bytes): A = 128x32 fp16, B = 256x32 fp16 (padded rows)
constexpr int A_SM_BYTES  = 128 * SPH * 2;          // 10240
constexpr int B_SM_BYTES  = 256 * SPH * 2;          // 20480
constexpr int STAGE_BYTES = A_SM_BYTES + B_SM_BYTES; // 30720
constexpr int OFF_Bt      = A_SM_BYTES;

// Float-indexed regions after the two stage buffers
constexpr int MASKF   = (2 * STAGE_BYTES) / 4;   // 15360 (1024 floats)
constexpr int COLWF   = MASKF + 1024;            // 4(wm) x 256 floats
constexpr int ROWREDF = COLWF + 1024;            // 128 x 4(wn) floats
constexpr int REDF    = ROWREDF + 512;           // 64 floats (16 warps x 4)
constexpr int SMEM_BYTES = (REDF + 64) * 4;      // 71936

// ---------------------------------------------------------------------------
// Helpers
// ---------------------------------------------------------------------------
__device__ __forceinline__ uint32_t smem_u32(const void* p) {
    uint32_t a;
    asm("{ .reg .u64 t; cvta.to.shared.u64 t, %1; cvt.u32.u64 %0, t; }"
        : "=r"(a) : "l"(p));
    return a;
}

__device__ __forceinline__ void ldm4(uint32_t* r, uint32_t addr) {
    asm volatile("ldmatrix.sync.aligned.m8n8.x4.shared.b16 {%0,%1,%2,%3}, [%4];"
                 : "=r"(r[0]), "=r"(r[1]), "=r"(r[2]), "=r"(r[3]) : "r"(addr));
}

// m16n8k16 row.col fp16 mma, fp32 accumulate (C==D)
__device__ __forceinline__ void mma16(float* c, const uint32_t* a,
                                      uint32_t b0, uint32_t b1) {
    asm volatile(
        "mma.sync.aligned.m16n8k16.row.col.f32.f16.f16.f32 "
        "{%0,%1,%2,%3}, {%4,%5,%6,%7}, {%8,%9}, {%0,%1,%2,%3};"
        : "+f"(c[0]), "+f"(c[1]), "+f"(c[2]), "+f"(c[3])
        : "r"(a[0]), "r"(a[1]), "r"(a[2]), "r"(a[3]), "r"(b0), "r"(b1));
}

// ---------------------------------------------------------------------------
// Kernel: one CTA per batch; 512 threads = 16 warps (4 M x 4 N).
// Warp tile m32 x n64. CTA tile 128(M) x 256(N). K chunked by 32 (2 x k16).
// fp16 operands converted in the loader; fp32 accumulators.
// ---------------------------------------------------------------------------
__global__ void __launch_bounds__(512, 1)
hrpa_kernel(const float* __restrict__ patch,   // (B, N, C)
            const float* __restrict__ word,    // (B, M, C)
            const float* __restrict__ mask,    // (B, N)
            float* __restrict__ out)           // (B, 1)
{
    extern __shared__ char smc[];
    float* fsm = reinterpret_cast<float*>(smc);
    const uint32_t smb = smem_u32(smc);

    const int tid  = threadIdx.x;
    const int lane = tid & 31;
    const int w    = tid >> 5;     // 0..15
    const int wm   = w & 3;        // M direction (rows wm*32 .. +31)
    const int wn   = w >> 2;       // N direction (cols wn*64 .. +63)
    const int g    = lane >> 2;    // quad group 0..7
    const int tig  = lane & 3;     // thread in group
    const int b    = blockIdx.x;

    // ldmatrix per-thread offsets (half units)
    const int mi = lane >> 3, r8 = lane & 7;
    const int aoff = (((mi & 1) << 3) + r8) * SPH + ((mi >> 1) << 3);
    const int boff = (((mi >> 1) << 3) + r8) * SPH + ((mi & 1) << 3);

    const float* wbase = word  + (size_t)b * M_ * C_;
    const float* pbase = patch + (size_t)b * N_ * C_;

    // loader mapping: 512 threads, slot = p*512 + tid -> row = slot>>3, vec = tid&7
    const int lr = tid >> 3;   // 0..63
    const int lv = tid & 7;

    // ---- mask -> smem, accumulate mask sum ----
    float masksum = 0.f;
    for (int i = tid; i < N_; i += 512) {
        float m = mask[b * N_ + i];
        fsm[MASKF + i] = m;
        masksum += m;
    }

    auto load_regs = [&](int gq, float4* stA, float4* stB) {
        const int nt = gq >> 4;
        const int k0 = (gq & 15) * KC;
        #pragma unroll
        for (int p = 0; p < 2; p++) {   // A: 128 rows
            const int r = p * 64 + lr;
            stA[p] = *(const float4*)(wbase + (size_t)r * C_ + k0 + lv * 4);
        }
        #pragma unroll
        for (int p = 0; p < 4; p++) {   // B: 256 rows
            const int r = p * 64 + lr;
            stB[p] = *(const float4*)(pbase + (size_t)(nt * NTILE + r) * C_ + k0 + lv * 4);
        }
    };
    auto sts_stage = [&](int buf, const float4* stA, const float4* stB) {
        char* base = smc + buf * STAGE_BYTES;
        #pragma unroll
        for (int p = 0; p < 2; p++) {
            const int r = p * 64 + lr;
            __half2 h0 = __floats2half2_rn(stA[p].x, stA[p].y);
            __half2 h1 = __floats2half2_rn(stA[p].z, stA[p].w);
            *(uint2*)(base + (r * SPH + lv * 4) * 2) =
                make_uint2(*(uint32_t*)&h0, *(uint32_t*)&h1);
        }
        #pragma unroll
        for (int p = 0; p < 4; p++) {
            const int r = p * 64 + lr;
            __half2 h0 = __floats2half2_rn(stB[p].x, stB[p].y);
            __half2 h1 = __floats2half2_rn(stB[p].z, stB[p].w);
            *(uint2*)(base + OFF_Bt + (r * SPH + lv * 4) * 2) =
                make_uint2(*(uint32_t*)&h0, *(uint32_t*)&h1);
        }
    };

    // prologue: chunk 0 -> buffer 0
    {
        float4 sA[2], sB[4];
        load_regs(0, sA, sB);
        sts_stage(0, sA, sB);
    }
    __syncthreads();

    float rmax[4] = {-3.0e38f, -3.0e38f, -3.0e38f, -3.0e38f};
    float colsum = 0.f;

    for (int nt = 0; nt < NTILES; nt++) {
        float acc[2][8][4];
        #pragma unroll
        for (int mt = 0; mt < 2; mt++)
            #pragma unroll
            for (int j = 0; j < 8; j++)
                #pragma unroll
                for (int q = 0; q < 4; q++) acc[mt][j][q] = 0.f;

        for (int kc = 0; kc < KCH; kc++) {
            const int gq  = nt * KCH + kc;
            const int buf = gq & 1;
            const bool more = (gq + 1 < GTOT);

            // prefetch next chunk into registers (independent of MMAs below)
            float4 sA[2], sB[4];
            if (more) load_regs(gq + 1, sA, sB);

            // ---- MMAs on chunk gq from smem[buf] ----
            const uint32_t abase = smb + buf * STAGE_BYTES;
            const uint32_t bbase = abase + OFF_Bt;
            #pragma unroll
            for (int ks = 0; ks < 2; ks++) {
                uint32_t A0[4], A1[4];
                ldm4(A0, abase + (uint32_t)(((wm * 32     ) * SPH) + aoff + ks * 16) * 2);
                ldm4(A1, abase + (uint32_t)(((wm * 32 + 16) * SPH) + aoff + ks * 16) * 2);
                #pragma unroll
                for (int jj = 0; jj < 4; jj++) {
                    uint32_t Bf[4];
                    ldm4(Bf, bbase + (uint32_t)(((wn * 64 + jj * 16) * SPH) + boff + ks * 16) * 2);
                    mma16(acc[0][jj * 2    ], A0, Bf[0], Bf[1]);
                    mma16(acc[1][jj * 2    ], A1, Bf[0], Bf[1]);
                    mma16(acc[0][jj * 2 + 1], A0, Bf[2], Bf[3]);
                    mma16(acc[1][jj * 2 + 1], A1, Bf[2], Bf[3]);
                }
            }

            // store next chunk to the other buffer, then one sync
            if (more) sts_stage(buf ^ 1, sA, sB);
            __syncthreads();
        }

        // ---- epilogue for this ntile ----
        // Thread owns rows {wm*32+mt*16+g, +8}, cols {wn*64+j*8+2tig, +1}.
        float colpart[16];
        #pragma unroll
        for (int j = 0; j < 8; j++) {
            #pragma unroll
            for (int cc = 0; cc < 2; cc++) {
                const int col = wn * 64 + j * 8 + 2 * tig + cc;
                const float pen = 1000.f * (1.f - fsm[MASKF + nt * NTILE + col]);
                float vmax = -3.0e38f;
                #pragma unroll
                for (int mt = 0; mt < 2; mt++) {
                    float v0 = acc[mt][j][cc];      // row m0+g
                    float v1 = acc[mt][j][cc + 2];  // row m0+8+g
                    v0 = v0 > 0.f ? v0 : 0.1f * v0;
                    v1 = v1 > 0.f ? v1 : 0.1f * v1;
                    rmax[mt * 2 + 0] = fmaxf(rmax[mt * 2 + 0], v0 - pen);
                    rmax[mt * 2 + 1] = fmaxf(rmax[mt * 2 + 1], v1 - pen);
                    vmax = fmaxf(vmax, fmaxf(v0, v1));
                }
                colpart[j * 2 + cc] = vmax;
            }
        }
        // column max across the 8 quad-groups (lanes differing in g)
        #pragma unroll
        for (int off = 4; off <= 16; off <<= 1)
            #pragma unroll
            for (int i = 0; i < 16; i++)
                colpart[i] = fmaxf(colpart[i], __shfl_xor_sync(0xffffffffu, colpart[i], off));
        if (g == 0) {
            #pragma unroll
            for (int j = 0; j < 8; j++)
                #pragma unroll
                for (int cc = 0; cc < 2; cc++)
                    fsm[COLWF + wm * NTILE + wn * 64 + j * 8 + 2 * tig + cc] =
                        colpart[j * 2 + cc];
        }
        __syncthreads();
        if (tid < NTILE) {
            const float cm = fmaxf(
                fmaxf(fsm[COLWF + tid],             fsm[COLWF + NTILE + tid]),
                fmaxf(fsm[COLWF + 2 * NTILE + tid], fsm[COLWF + 3 * NTILE + tid]));
            colsum += cm * fsm[MASKF + nt * NTILE + tid];
        }
        __syncthreads();
    }

    // ---- row-max combine (within quad, then across wn groups) ----
    #pragma unroll
    for (int off = 1; off <= 2; off <<= 1)
        #pragma unroll
        for (int i = 0; i < 4; i++)
            rmax[i] = fmaxf(rmax[i], __shfl_xor_sync(0xffffffffu, rmax[i], off));
    if (tig == 0) {
        #pragma unroll
        for (int mt = 0; mt < 2; mt++) {
            fsm[ROWREDF + (wm * 32 + mt * 16 +     g) * 4 + wn] = rmax[mt * 2 + 0];
            fsm[ROWREDF + (wm * 32 + mt * 16 + 8 + g) * 4 + wn] = rmax[mt * 2 + 1];
        }
    }
    __syncthreads();

    float rpart = 0.f;
    if (tid < 128) {
        rpart = fmaxf(fmaxf(fsm[ROWREDF + tid * 4 + 0], fsm[ROWREDF + tid * 4 + 1]),
                      fmaxf(fsm[ROWREDF + tid * 4 + 2], fsm[ROWREDF + tid * 4 + 3]));
    }

    // ---- block reduction of rpart / colsum / masksum ----
    #pragma unroll
    for (int off = 16; off > 0; off >>= 1) {
        rpart   += __shfl_down_sync(0xffffffffu, rpart,   off);
        colsum  += __shfl_down_sync(0xffffffffu, colsum,  off);
        masksum += __shfl_down_sync(0xffffffffu, masksum, off);
    }
    if (lane == 0) {
        fsm[REDF + w * 4 + 0] = rpart;
        fsm[REDF + w * 4 + 1] = colsum;
        fsm[REDF + w * 4 + 2] = masksum;
    }
    __syncthreads();
    if (tid == 0) {
        float rs = 0.f, cs = 0.f, ms = 0.f;
        #pragma unroll
        for (int i = 0; i < 16; i++) {
            rs += fsm[REDF + i * 4 + 0];
            cs += fsm[REDF + i * 4 + 1];
            ms += fsm[REDF + i * 4 + 2];
        }
        out[b] = rs * (1.f / 128.f) + cs / (ms + 1e-8f);
    }
}

// ---------------------------------------------------------------------------
// Host launch
// ---------------------------------------------------------------------------
extern "C" void kernel_launch(void* const* d_in, const int* in_sizes, int n_in,
                              void* d_out, int out_size)
{
    (void)in_sizes; (void)n_in; (void)out_size;
    const float* patch = (const float*)d_in[0];  // (B, N, C)
    const float* word  = (const float*)d_in[1];  // (B, M, C)
    const float* mask  = (const float*)d_in[2];  // (B, N)
    float* out = (float*)d_out;                  // (B, 1)

    cudaFuncSetAttribute(hrpa_kernel,
                         cudaFuncAttributeMaxDynamicSharedMemorySize, SMEM_BYTES);
    hrpa_kernel<<<B_, 512, SMEM_BYTES>>>(patch, word, mask, out);
}